// round 1
// baseline (speedup 1.0000x reference)
#include <cuda_runtime.h>
#include <stdint.h>

// Problem constants (fixed by the dataset)
#define NB     16
#define TT     2048
#define SS     2048
#define HH     64
#define KSEL   64
#define INITW  16
#define NITER  7          // log2(SS / INITW)

__global__ __launch_bounds__(128, 16)
void tree_attn_kernel(const float* __restrict__ q,
                      const float* __restrict__ k,
                      const float* __restrict__ v,
                      float* __restrict__ out)
{
    __shared__ int                zcur[128];   // expanded candidates
    __shared__ float              sc[128];     // candidate scores
    __shared__ unsigned long long skey[128];   // bitonic sort keys
    __shared__ int                zsel[KSEL];  // selected candidates
    __shared__ float              ssel[KSEL];  // selected scores
    __shared__ int                pos_s[KSEL];
    __shared__ float              pvec[KSEL];
    __shared__ float              red[2];      // max, sum

    const int row  = blockIdx.x;
    const int n    = row >> 11;       // / TT
    const int t    = row & (TT - 1);
    const float tsrc = (float)(SS - TT + 1 + t);   // = t+1 here

    const int tid  = threadIdx.x;
    const int lane = tid & 31;
    const int l16  = lane & 15;
    const int hw   = tid >> 4;        // half-warp id 0..7

    // this lane's q chunk (4 floats); each half-warp covers the full H=64 row
    const float4* qrow = (const float4*)(q + ((size_t)n * TT + t) * HH);
    const float4  q4   = qrow[l16];

    // initial candidate grid
    if (tid < INITW) zsel[tid] = tid;
    int cnt = INITW;
    int w   = INITW;

    #pragma unroll 1
    for (int it = 0; it < NITER; ++it) {
        const int w2   = w << 1;
        const int cnt2 = cnt << 1;

        __syncthreads();
        // expand: children interleaved exactly like jnp.stack(...).reshape
        if (tid < cnt) {
            int z = zsel[tid];
            zcur[2 * tid]     = 2 * z;
            zcur[2 * tid + 1] = 2 * z + 1;
        }
        __syncthreads();

        const float r = tsrc / (float)w2;   // exact (power-of-2 divisor)

        // score candidates: half-warp hw handles c = hw, hw+8, ...
        // 16 lanes cooperatively load the 256B key row (coalesced) + shuffle-reduce.
        for (int c = hw; c < cnt2; c += 8) {
            int z = zcur[c];
            float pf = (float)z * r;        // exact product (< 2^23)
            int pos = (int)rintf(pf);       // round half-to-even, matches jnp.round
            pos = max(0, min(pos, SS - 1));
            const float4* krow = (const float4*)(k + ((size_t)n * SS + pos) * HH);
            float4 k4 = krow[l16];
            float part = q4.x * k4.x + q4.y * k4.y + q4.z * k4.z + q4.w * k4.w;
            part += __shfl_xor_sync(0xffffffffu, part, 1);
            part += __shfl_xor_sync(0xffffffffu, part, 2);
            part += __shfl_xor_sync(0xffffffffu, part, 4);
            part += __shfl_xor_sync(0xffffffffu, part, 8);
            if (l16 == 0) sc[c] = part;
        }
        __syncthreads();

        // build sort keys: descending by (score, -index) == ascending on complement
        {
            unsigned long long mykey;
            if (tid < cnt2) {
                unsigned int u  = __float_as_uint(sc[tid]);
                unsigned int su = (u & 0x80000000u) ? ~u : (u | 0x80000000u);
                mykey = ~(((unsigned long long)su << 8) |
                           (unsigned long long)(127 - tid));
            } else {
                mykey = ~0ull;   // pad: sinks to the end
            }
            skey[tid] = mykey;
        }

        // bitonic ascending sort of 128 elements (1 element / thread)
        #pragma unroll
        for (int kk = 2; kk <= 128; kk <<= 1) {
            #pragma unroll
            for (int j = kk >> 1; j > 0; j >>= 1) {
                __syncthreads();
                int ixj = tid ^ j;
                if (ixj > tid) {
                    unsigned long long a = skey[tid], b = skey[ixj];
                    bool up = ((tid & kk) == 0);
                    if (up ? (a > b) : (a < b)) { skey[tid] = b; skey[ixj] = a; }
                }
            }
        }
        __syncthreads();

        const int keep = min(KSEL, cnt2);
        if (tid < keep) {
            unsigned long long kk2 = ~skey[tid];
            int idx = 127 - (int)(kk2 & 0xFFu);
            zsel[tid] = zcur[idx];
            ssel[tid] = sc[idx];
        }
        cnt = keep;
        w   = w2;
    }
    __syncthreads();

    // ---- final attention over the KSEL kept candidates ----
    float a_val = -1e9f;
    bool  valid = false;
    if (tid < KSEL) {
        int z = zsel[tid];
        float r = tsrc / (float)SS;     // final w == SS
        int pos = (int)rintf((float)z * r);
        pos = max(0, min(pos, SS - 1));
        pos_s[tid] = pos;
        valid = ((float)pos < tsrc);
        a_val = valid ? ssel[tid] * 0.125f : -1e9f;   // 1/sqrt(64)
        sc[tid] = a_val;
    }
    __syncthreads();
    if (tid < 32) {
        float x = fmaxf(sc[tid], sc[tid + 32]);
        x = fmaxf(x, __shfl_xor_sync(0xffffffffu, x, 16));
        x = fmaxf(x, __shfl_xor_sync(0xffffffffu, x, 8));
        x = fmaxf(x, __shfl_xor_sync(0xffffffffu, x, 4));
        x = fmaxf(x, __shfl_xor_sync(0xffffffffu, x, 2));
        x = fmaxf(x, __shfl_xor_sync(0xffffffffu, x, 1));
        if (tid == 0) red[0] = x;
    }
    __syncthreads();
    const float m = red[0];
    float e = 0.0f;
    if (tid < KSEL) {
        e = valid ? expf(a_val - m) : 0.0f;   // invalid: ref exp underflows to 0 too
        sc[tid] = e;
    }
    __syncthreads();
    if (tid < 32) {
        float x = sc[tid] + sc[tid + 32];
        x += __shfl_xor_sync(0xffffffffu, x, 16);
        x += __shfl_xor_sync(0xffffffffu, x, 8);
        x += __shfl_xor_sync(0xffffffffu, x, 4);
        x += __shfl_xor_sync(0xffffffffu, x, 2);
        x += __shfl_xor_sync(0xffffffffu, x, 1);
        if (tid == 0) red[1] = x;
    }
    __syncthreads();
    if (tid < KSEL) {
        float s = red[1];
        pvec[tid] = (s > 0.0f) ? (e / s) : 0.0f;   // all-invalid -> 0, matches ref
    }
    __syncthreads();

    // out[h] = sum_k p[k] * V[n, pos[k], h] ; one thread per h, coalesced loads
    if (tid < HH) {
        const float* vb = v + (size_t)n * SS * HH + tid;
        float acc = 0.0f;
        #pragma unroll 4
        for (int kk = 0; kk < KSEL; ++kk) {
            acc += pvec[kk] * vb[(size_t)pos_s[kk] * HH];
        }
        out[((size_t)n * TT + t) * HH + tid] = acc;
    }
}

extern "C" void kernel_launch(void* const* d_in, const int* in_sizes, int n_in,
                              void* d_out, int out_size)
{
    const float* q = (const float*)d_in[0];
    const float* k = (const float*)d_in[1];
    const float* v = (const float*)d_in[2];
    float* out = (float*)d_out;
    (void)in_sizes; (void)n_in; (void)out_size;

    tree_attn_kernel<<<NB * TT, 128>>>(q, k, v, out);
}

// round 2
// speedup vs baseline: 1.8975x; 1.8975x over previous
#include <cuda_runtime.h>
#include <stdint.h>

// Problem constants (fixed by the dataset)
#define NB     16
#define TT     2048
#define SS     2048
#define HH     64
#define KSEL   64
#define INITW  16
#define NITER  7          // log2(SS / INITW)

__device__ __forceinline__ unsigned long long ullmin2(unsigned long long a, unsigned long long b) {
    return a < b ? a : b;
}
__device__ __forceinline__ unsigned long long ullmax2(unsigned long long a, unsigned long long b) {
    return a > b ? a : b;
}

__global__ __launch_bounds__(128, 16)
void tree_attn_kernel(const float* __restrict__ q,
                      const float* __restrict__ k,
                      const float* __restrict__ v,
                      float* __restrict__ out)
{
    __shared__ int                zcur[128];   // expanded candidates
    __shared__ float              sc[128];     // candidate scores
    __shared__ unsigned long long skey[128];   // cross-warp sort exchange
    __shared__ int                zsel[KSEL];  // selected candidates
    __shared__ float              ssel[KSEL];  // selected scores
    __shared__ int                pos_s[KSEL];
    __shared__ float              pvec[KSEL];
    __shared__ float              red[2];      // max, sum

    const int row  = blockIdx.x;
    const int n    = row >> 11;       // / TT
    const int t    = row & (TT - 1);
    const float tsrc = (float)(SS - TT + 1 + t);   // = t+1 here

    const int tid  = threadIdx.x;
    const int lane = tid & 31;
    const int l16  = lane & 15;
    const int hw   = tid >> 4;        // half-warp id 0..7

    // this lane's q chunk (4 floats); each half-warp covers the full H=64 row
    const float4* qrow = (const float4*)(q + ((size_t)n * TT + t) * HH);
    const float4  q4   = qrow[l16];

    // initial candidate grid
    if (tid < INITW) zsel[tid] = tid;
    int cnt = INITW;
    int w   = INITW;

    #pragma unroll 1
    for (int it = 0; it < NITER; ++it) {
        const int w2   = w << 1;
        const int cnt2 = cnt << 1;

        __syncthreads();
        // expand: children interleaved exactly like jnp.stack(...).reshape.
        // Even child (2z) has pos(2z, w2) == pos(z, w) bit-exactly -> reuse
        // the parent's score (iterations >= 1).
        if (tid < cnt) {
            int z = zsel[tid];
            zcur[2 * tid]     = 2 * z;
            zcur[2 * tid + 1] = 2 * z + 1;
            if (it > 0) sc[2 * tid] = ssel[tid];
        }
        __syncthreads();

        const float r = tsrc / (float)w2;   // exact (power-of-2 divisor)

        // score candidates: 16 lanes cooperatively load a 256B key row
        // (coalesced float4) and shuffle-reduce the dot product.
        if (it == 0) {
            // no parent scores yet: score all 32 children
            for (int c = hw; c < cnt2; c += 8) {
                int z = zcur[c];
                int pos = (int)rintf((float)z * r);
                pos = max(0, min(pos, SS - 1));
                const float4* krow = (const float4*)(k + ((size_t)n * SS + pos) * HH);
                float4 k4 = krow[l16];
                float part = q4.x * k4.x + q4.y * k4.y + q4.z * k4.z + q4.w * k4.w;
                part += __shfl_xor_sync(0xffffffffu, part, 1);
                part += __shfl_xor_sync(0xffffffffu, part, 2);
                part += __shfl_xor_sync(0xffffffffu, part, 4);
                part += __shfl_xor_sync(0xffffffffu, part, 8);
                if (l16 == 0) sc[c] = part;
            }
        } else {
            // only odd children (2z+1) are new
            for (int i = hw; i < cnt; i += 8) {
                int c = 2 * i + 1;
                int z = zcur[c];
                int pos = (int)rintf((float)z * r);
                pos = max(0, min(pos, SS - 1));
                const float4* krow = (const float4*)(k + ((size_t)n * SS + pos) * HH);
                float4 k4 = krow[l16];
                float part = q4.x * k4.x + q4.y * k4.y + q4.z * k4.z + q4.w * k4.w;
                part += __shfl_xor_sync(0xffffffffu, part, 1);
                part += __shfl_xor_sync(0xffffffffu, part, 2);
                part += __shfl_xor_sync(0xffffffffu, part, 4);
                part += __shfl_xor_sync(0xffffffffu, part, 8);
                if (l16 == 0) sc[c] = part;
            }
        }
        __syncthreads();

        // build sort key: descending by (score, -index) == ascending on complement
        unsigned long long key;
        if (tid < cnt2) {
            unsigned int u  = __float_as_uint(sc[tid]);
            unsigned int su = (u & 0x80000000u) ? ~u : (u | 0x80000000u);
            key = ~(((unsigned long long)su << 8) |
                     (unsigned long long)(127 - tid));
        } else {
            key = ~0ull;   // pad: sinks to the end
        }

        // bitonic ascending sort, keys in registers; shfl for intra-warp
        // stages, shared memory only for the 3 cross-warp stages.
        #pragma unroll
        for (int kk = 2; kk <= 128; kk <<= 1) {
            #pragma unroll
            for (int j = kk >> 1; j > 0; j >>= 1) {
                bool take_min = (((tid & j) == 0) == ((tid & kk) == 0));
                unsigned long long p;
                if (j >= 32) {
                    skey[tid] = key;
                    __syncthreads();
                    p = skey[tid ^ j];
                    __syncthreads();
                } else {
                    p = __shfl_xor_sync(0xffffffffu, key, j);
                }
                key = take_min ? ullmin2(key, p) : ullmax2(key, p);
            }
        }
        skey[tid] = key;
        __syncthreads();

        const int keep = min(KSEL, cnt2);
        if (tid < keep) {
            unsigned long long kk2 = ~skey[tid];
            int idx = 127 - (int)(kk2 & 0xFFu);
            zsel[tid] = zcur[idx];
            // recover exact score bits from the sort key (bijective encoding)
            unsigned int su = (unsigned int)(kk2 >> 8);
            unsigned int u  = (su & 0x80000000u) ? (su & 0x7FFFFFFFu) : ~su;
            ssel[tid] = __uint_as_float(u);
        }
        cnt = keep;
        w   = w2;
    }
    __syncthreads();

    // ---- final attention over the KSEL kept candidates ----
    float a_val = -1e9f;
    bool  valid = false;
    if (tid < KSEL) {
        int z = zsel[tid];
        float r = tsrc / (float)SS;     // final w == SS
        int pos = (int)rintf((float)z * r);
        pos = max(0, min(pos, SS - 1));
        pos_s[tid] = pos;
        valid = ((float)pos < tsrc);
        a_val = valid ? ssel[tid] * 0.125f : -1e9f;   // 1/sqrt(64)
        sc[tid] = a_val;
    }
    __syncthreads();
    if (tid < 32) {
        float x = fmaxf(sc[tid], sc[tid + 32]);
        x = fmaxf(x, __shfl_xor_sync(0xffffffffu, x, 16));
        x = fmaxf(x, __shfl_xor_sync(0xffffffffu, x, 8));
        x = fmaxf(x, __shfl_xor_sync(0xffffffffu, x, 4));
        x = fmaxf(x, __shfl_xor_sync(0xffffffffu, x, 2));
        x = fmaxf(x, __shfl_xor_sync(0xffffffffu, x, 1));
        if (tid == 0) red[0] = x;
    }
    __syncthreads();
    const float m = red[0];
    float e = 0.0f;
    if (tid < KSEL) {
        e = valid ? expf(a_val - m) : 0.0f;   // invalid: ref exp underflows to 0 too
        sc[tid] = e;
    }
    __syncthreads();
    if (tid < 32) {
        float x = sc[tid] + sc[tid + 32];
        x += __shfl_xor_sync(0xffffffffu, x, 16);
        x += __shfl_xor_sync(0xffffffffu, x, 8);
        x += __shfl_xor_sync(0xffffffffu, x, 4);
        x += __shfl_xor_sync(0xffffffffu, x, 2);
        x += __shfl_xor_sync(0xffffffffu, x, 1);
        if (tid == 0) red[1] = x;
    }
    __syncthreads();
    if (tid < KSEL) {
        float s = red[1];
        pvec[tid] = (s > 0.0f) ? (e / s) : 0.0f;   // all-invalid -> 0, matches ref
    }
    __syncthreads();

    // out[h] = sum_k p[k] * V[n, pos[k], h] ; one thread per h, coalesced loads
    if (tid < HH) {
        const float* vb = v + (size_t)n * SS * HH + tid;
        float acc = 0.0f;
        #pragma unroll 4
        for (int kk = 0; kk < KSEL; ++kk) {
            acc += pvec[kk] * vb[(size_t)pos_s[kk] * HH];
        }
        out[((size_t)n * TT + t) * HH + tid] = acc;
    }
}

extern "C" void kernel_launch(void* const* d_in, const int* in_sizes, int n_in,
                              void* d_out, int out_size)
{
    const float* q = (const float*)d_in[0];
    const float* k = (const float*)d_in[1];
    const float* v = (const float*)d_in[2];
    float* out = (float*)d_out;
    (void)in_sizes; (void)n_in; (void)out_size;

    tree_attn_kernel<<<NB * TT, 128>>>(q, k, v, out);
}

// round 3
// speedup vs baseline: 3.0227x; 1.5930x over previous
#include <cuda_runtime.h>
#include <stdint.h>

// Problem constants (fixed by the dataset)
#define NBATCH 16
#define TT     2048
#define SS     2048
#define HH     64
#define KSEL   64

__device__ __forceinline__ unsigned long long umax64(unsigned long long a, unsigned long long b) {
    return a > b ? a : b;
}
__device__ __forceinline__ unsigned long long umin64(unsigned long long a, unsigned long long b) {
    return a < b ? a : b;
}

// key = (sortable_score << 8) | (127 - expanded_idx)
// numeric DESC order == desc by score, ties broken by ascending index (lax.top_k)
__device__ __forceinline__ unsigned long long enc_key(float s, int idx) {
    unsigned int u  = __float_as_uint(s);
    unsigned int su = (u & 0x80000000u) ? ~u : (u | 0x80000000u);
    return ((unsigned long long)su << 8) | (unsigned long long)(127 - idx);
}

__global__ __launch_bounds__(64)
void tree_attn_kernel(const float* __restrict__ q,
                      const float* __restrict__ kmat,
                      const float* __restrict__ v,
                      float* __restrict__ out)
{
    __shared__ float              sc_odd[64];  // fresh (odd-child) scores
    __shared__ unsigned long long xkey[64];    // cross-warp sort exchange
    __shared__ int                zpar[64];    // parent z values
    __shared__ int                pos_s[64];
    __shared__ float              pvec[64];
    __shared__ float              red[4];

    const int row  = blockIdx.x;
    const int n    = row >> 11;
    const int t    = row & (TT - 1);
    const float tsrc = (float)(t + 1);

    const int g    = threadIdx.x;   // 0..63
    const int lane = g & 31;
    const int l16  = g & 15;
    const int hwg  = g >> 4;        // half-warp 0..3

    const float* kbase = kmat + (size_t)n * SS * HH;
    const float4 q4 = ((const float4*)(q + ((size_t)(n * TT + t)) * HH))[l16];

    unsigned long long key = 0;  // selection key (score packed in bits [8,40))
    int zsel = 0;

    // ---------------- iteration 0: 32 fresh candidates, w2=32 ----------------
    {
        const float r = tsrc * (1.0f / 32.0f);
        for (int c = hwg; c < 32; c += 4) {
            int pos = min((int)rintf((float)c * r), SS - 1);
            const float4 k4 = ((const float4*)(kbase + (size_t)pos * HH))[l16];
            float part = q4.x * k4.x + q4.y * k4.y + q4.z * k4.z + q4.w * k4.w;
            part += __shfl_xor_sync(0xffffffffu, part, 1);
            part += __shfl_xor_sync(0xffffffffu, part, 2);
            part += __shfl_xor_sync(0xffffffffu, part, 4);
            part += __shfl_xor_sync(0xffffffffu, part, 8);
            if (l16 == 0) sc_odd[c] = part;
        }
        __syncthreads();
        if (g < 32) {   // warp0: 15-stage desc bitonic sort of 32
            key = enc_key(sc_odd[lane], lane);   // expanded idx == z at level 0
            #pragma unroll
            for (int kk = 2; kk <= 32; kk <<= 1)
                #pragma unroll
                for (int j = kk >> 1; j > 0; j >>= 1) {
                    unsigned long long p = __shfl_xor_sync(0xffffffffu, key, j);
                    bool mx = (((lane & j) == 0) == ((lane & kk) == 0));
                    key = mx ? umax64(key, p) : umin64(key, p);
                }
            zsel = 127 - (int)(key & 0xFFu);
        }
        __syncthreads();   // sc_odd reuse barrier
    }

    // ---------------- iteration 1: 32 parents -> keep all 64, w2=64 ----------
    {
        if (g < 32) zpar[g] = zsel;
        __syncthreads();
        const float r = tsrc * (1.0f / 64.0f);
        for (int i = hwg; i < 32; i += 4) {
            int z = 2 * zpar[i] + 1;                       // odd child only
            int pos = min((int)rintf((float)z * r), SS - 1);
            const float4 k4 = ((const float4*)(kbase + (size_t)pos * HH))[l16];
            float part = q4.x * k4.x + q4.y * k4.y + q4.z * k4.z + q4.w * k4.w;
            part += __shfl_xor_sync(0xffffffffu, part, 1);
            part += __shfl_xor_sync(0xffffffffu, part, 2);
            part += __shfl_xor_sync(0xffffffffu, part, 4);
            part += __shfl_xor_sync(0xffffffffu, part, 8);
            if (l16 == 0) sc_odd[i] = part;
        }
        __syncthreads();
        // warp0 sorts the 32 odd keys desc
        unsigned long long okey = 0;
        if (g < 32) {
            okey = enc_key(sc_odd[lane], 2 * lane + 1);
            #pragma unroll
            for (int kk = 2; kk <= 32; kk <<= 1)
                #pragma unroll
                for (int j = kk >> 1; j > 0; j >>= 1) {
                    unsigned long long p = __shfl_xor_sync(0xffffffffu, okey, j);
                    bool mx = (((lane & j) == 0) == ((lane & kk) == 0));
                    okey = mx ? umax64(okey, p) : umin64(okey, p);
                }
            xkey[lane] = okey;
            // even child keeps parent score; new expanded idx = 2g
            key = (key & ~0xFFull) | (unsigned long long)(127 - 2 * g);
        }
        __syncthreads();
        if (g >= 32) key = xkey[63 - g];   // reversed odds -> bitonic 64
        __syncthreads();
        // 6-stage desc merge over 64
        #pragma unroll
        for (int j = 32; j > 0; j >>= 1) {
            unsigned long long p;
            if (j == 32) { xkey[g] = key; __syncthreads(); p = xkey[g ^ 32]; __syncthreads(); }
            else          p = __shfl_xor_sync(0xffffffffu, key, j);
            bool mx = ((g & j) == 0);
            key = mx ? umax64(key, p) : umin64(key, p);
        }
        int e = 127 - (int)(key & 0xFFu);
        zsel = 2 * zpar[e >> 1] + (e & 1);
    }

    // ---------------- iterations 2..6: 64 parents -> top-64 of 128 -----------
    #pragma unroll 1
    for (int it = 2; it < 7; ++it) {
        __syncthreads();                  // protect zpar read from prev iter
        zpar[g] = zsel;
        __syncthreads();
        const float r = tsrc / (float)(32 << it);
        for (int i = hwg; i < 64; i += 4) {
            int z = 2 * zpar[i] + 1;                       // odd children fresh
            int pos = min((int)rintf((float)z * r), SS - 1);
            const float4 k4 = ((const float4*)(kbase + (size_t)pos * HH))[l16];
            float part = q4.x * k4.x + q4.y * k4.y + q4.z * k4.z + q4.w * k4.w;
            part += __shfl_xor_sync(0xffffffffu, part, 1);
            part += __shfl_xor_sync(0xffffffffu, part, 2);
            part += __shfl_xor_sync(0xffffffffu, part, 4);
            part += __shfl_xor_sync(0xffffffffu, part, 8);
            if (l16 == 0) sc_odd[i] = part;
        }
        __syncthreads();

        // 21-stage desc bitonic sort of the 64 odd keys (2 warps)
        unsigned long long okey = enc_key(sc_odd[g], 2 * g + 1);
        #pragma unroll
        for (int kk = 2; kk <= 64; kk <<= 1)
            #pragma unroll
            for (int j = kk >> 1; j > 0; j >>= 1) {
                unsigned long long p;
                if (j == 32) { xkey[g] = okey; __syncthreads(); p = xkey[g ^ 32]; __syncthreads(); }
                else          p = __shfl_xor_sync(0xffffffffu, okey, j);
                bool mx = (((g & j) == 0) == ((g & kk) == 0));
                okey = mx ? umax64(okey, p) : umin64(okey, p);
            }

        // combine: evens (sorted desc, held in `key`) vs reversed odds
        xkey[g] = okey;
        key = (key & ~0xFFull) | (unsigned long long)(127 - 2 * g);  // even idx = 2g
        __syncthreads();
        key = umax64(key, xkey[63 - g]);   // top-64 multiset, bitonic sequence
        __syncthreads();
        // 6-stage desc merge -> sorted top-64
        #pragma unroll
        for (int j = 32; j > 0; j >>= 1) {
            unsigned long long p;
            if (j == 32) { xkey[g] = key; __syncthreads(); p = xkey[g ^ 32]; __syncthreads(); }
            else          p = __shfl_xor_sync(0xffffffffu, key, j);
            bool mx = ((g & j) == 0);
            key = mx ? umax64(key, p) : umin64(key, p);
        }
        int e = 127 - (int)(key & 0xFFu);
        zsel = 2 * zpar[e >> 1] + (e & 1);
    }

    // ---------------- final attention over the 64 kept candidates ------------
    {
        const float rf = tsrc * (1.0f / 2048.0f);
        int pos = min((int)rintf((float)zsel * rf), SS - 1);
        bool valid = ((float)pos < tsrc);
        unsigned int su = (unsigned int)(key >> 8);
        unsigned int u  = (su & 0x80000000u) ? (su & 0x7FFFFFFFu) : ~su;
        float score = __uint_as_float(u);
        float a = valid ? score * 0.125f : -1e9f;   // 1/sqrt(64)

        float m = a;
        m = fmaxf(m, __shfl_xor_sync(0xffffffffu, m, 16));
        m = fmaxf(m, __shfl_xor_sync(0xffffffffu, m, 8));
        m = fmaxf(m, __shfl_xor_sync(0xffffffffu, m, 4));
        m = fmaxf(m, __shfl_xor_sync(0xffffffffu, m, 2));
        m = fmaxf(m, __shfl_xor_sync(0xffffffffu, m, 1));
        if (lane == 0) red[g >> 5] = m;
        __syncthreads();
        m = fmaxf(red[0], red[1]);

        float e = valid ? expf(a - m) : 0.0f;   // invalid: ref exp underflows to 0
        float s = e;
        s += __shfl_xor_sync(0xffffffffu, s, 16);
        s += __shfl_xor_sync(0xffffffffu, s, 8);
        s += __shfl_xor_sync(0xffffffffu, s, 4);
        s += __shfl_xor_sync(0xffffffffu, s, 2);
        s += __shfl_xor_sync(0xffffffffu, s, 1);
        if (lane == 0) red[2 + (g >> 5)] = s;
        __syncthreads();
        s = red[2] + red[3];

        pvec[g]  = (s > 0.0f) ? (e / s) : 0.0f;  // all-invalid -> 0, matches ref
        pos_s[g] = pos;
        __syncthreads();

        // out[h] = sum_k p[k] * V[n, pos[k], h] ; thread g = h, coalesced loads
        const float* vb = v + (size_t)n * SS * HH + g;
        float acc = 0.0f;
        #pragma unroll 8
        for (int kk = 0; kk < KSEL; ++kk)
            acc = fmaf(pvec[kk], vb[(size_t)pos_s[kk] * HH], acc);
        out[((size_t)(n * TT + t)) * HH + g] = acc;
    }
}

extern "C" void kernel_launch(void* const* d_in, const int* in_sizes, int n_in,
                              void* d_out, int out_size)
{
    const float* q = (const float*)d_in[0];
    const float* k = (const float*)d_in[1];
    const float* v = (const float*)d_in[2];
    float* out = (float*)d_out;
    (void)in_sizes; (void)n_in; (void)out_size;

    tree_attn_kernel<<<NBATCH * TT, 64>>>(q, k, v, out);
}